// round 4
// baseline (speedup 1.0000x reference)
#include <cuda_runtime.h>
#include <cstdint>

#define N_NODES   100000
#define N_EDGES   1600000
#define EDGE_FEAT 16
#define EDGE_HID  32
#define NODE_FEAT 128
#define TM 128
#define KC 16

// Scratch (allocation-free rule: __device__ globals)
__device__ float g_wsum[N_NODES * EDGE_FEAT];  // sum over edges of ex * feats
__device__ float g_ssum[N_NODES];              // sum over edges of ex
__device__ float g_ctx [N_NODES * EDGE_HID];   // elu(c) per node

// ---- packed f32x2 helpers (FFMA2 path: only reachable via PTX fma.rn.f32x2)
__device__ __forceinline__ unsigned long long bcast2(float x) {
    unsigned long long r;
    uint32_t u = __float_as_uint(x);
    asm("mov.b64 %0, {%1, %1};" : "=l"(r) : "r"(u));
    return r;
}
__device__ __forceinline__ void ffma2(unsigned long long& acc,
                                      unsigned long long a, unsigned long long b) {
    asm("fma.rn.f32x2 %0, %1, %2, %0;" : "+l"(acc) : "l"(a), "l"(b));
}
__device__ __forceinline__ float2 unpack2(unsigned long long v) {
    uint32_t lo, hi;
    asm("mov.b64 {%0, %1}, %2;" : "=r"(lo), "=r"(hi) : "l"(v));
    return make_float2(__uint_as_float(lo), __uint_as_float(hi));
}

// ---------------------------------------------------------------- zero scratch
__global__ void zero_kernel() {
    int i = blockIdx.x * blockDim.x + threadIdx.x;
    int stride = gridDim.x * blockDim.x;
    float4 z = make_float4(0.f, 0.f, 0.f, 0.f);
    float4* a = reinterpret_cast<float4*>(g_wsum);
    for (int idx = i; idx < N_NODES * EDGE_FEAT / 4; idx += stride) a[idx] = z;
    float4* b = reinterpret_cast<float4*>(g_ssum);
    for (int idx = i; idx < N_NODES / 4; idx += stride) b[idx] = z;
}

// ------------------------------------------------- edge pass: scatter ex, ex*f
__global__ void edge_kernel(const float* __restrict__ logits,
                            const float4* __restrict__ feats4,
                            const int* __restrict__ dst) {
    int t = blockIdx.x * blockDim.x + threadIdx.x;
    int e = t >> 2;
    int q = t & 3;
    if (e >= N_EDGES) return;
    int d = dst[e];
    float ex = __expf(logits[e]);
    float4 f = feats4[e * 4 + q];
    f.x *= ex; f.y *= ex; f.z *= ex; f.w *= ex;
    float* p = g_wsum + d * EDGE_FEAT + q * 4;
    asm volatile("red.global.add.v4.f32 [%0], {%1,%2,%3,%4};"
                 :: "l"(p), "f"(f.x), "f"(f.y), "f"(f.z), "f"(f.w) : "memory");
    if (q == 0)
        asm volatile("red.global.add.f32 [%0], %1;"
                     :: "l"(g_ssum + d), "f"(ex) : "memory");
}

// --------------------------------- per-node: normalize, 16->32 GEMM, bias, elu
__global__ void ctx_kernel(const float* __restrict__ W_et,
                           const float* __restrict__ b_et) {
    __shared__ float Ws[EDGE_FEAT * EDGE_HID];
    __shared__ float bs[EDGE_HID];
    for (int i = threadIdx.x; i < EDGE_FEAT * EDGE_HID; i += blockDim.x) Ws[i] = W_et[i];
    if (threadIdx.x < EDGE_HID) bs[threadIdx.x] = b_et[threadIdx.x];
    __syncthreads();
    int n = blockIdx.x * blockDim.x + threadIdx.x;
    if (n >= N_NODES) return;
    float s = g_ssum[n];
    float inv = (s > 0.f) ? (1.f / s) : 0.f;
    float ind = (s > 0.f) ? 1.f : 0.f;
    float gv[EDGE_FEAT];
    const float4* gp = reinterpret_cast<const float4*>(g_wsum + n * EDGE_FEAT);
#pragma unroll
    for (int k4 = 0; k4 < 4; k4++) {
        float4 v = gp[k4];
        gv[k4 * 4 + 0] = v.x * inv; gv[k4 * 4 + 1] = v.y * inv;
        gv[k4 * 4 + 2] = v.z * inv; gv[k4 * 4 + 3] = v.w * inv;
    }
    float c[EDGE_HID];
#pragma unroll
    for (int j = 0; j < EDGE_HID; j++) c[j] = ind * bs[j];
#pragma unroll
    for (int k = 0; k < EDGE_FEAT; k++) {
        float a = gv[k];
#pragma unroll
        for (int j = 0; j < EDGE_HID; j++) c[j] = fmaf(a, Ws[k * EDGE_HID + j], c[j]);
    }
    float4* outp = reinterpret_cast<float4*>(g_ctx + n * EDGE_HID);
#pragma unroll
    for (int j4 = 0; j4 < 8; j4++) {
        float4 v;
        float x;
        x = c[j4 * 4 + 0]; v.x = (x > 0.f) ? x : expm1f(x);
        x = c[j4 * 4 + 1]; v.y = (x > 0.f) ? x : expm1f(x);
        x = c[j4 * 4 + 2]; v.z = (x > 0.f) ? x : expm1f(x);
        x = c[j4 * 4 + 3]; v.w = (x > 0.f) ? x : expm1f(x);
        outp[j4] = v;
    }
}

// --------------------- fused MLP: relu([ctx|nf] @ W1 + b1) @ W2 + b2, relu
// 512 threads, tile 128x128, 4x8 microtile computed as 4x(4 f32x2 pairs)
// via fma.rn.f32x2 (FFMA2): 16 packed FMAs per k-step instead of 32 scalar.
// Weight quads are loaded as ulonglong2 (already lane-paired, no repacking).
__global__ __launch_bounds__(512, 1)
void mlp_kernel(const float4* __restrict__ nf4,
                const float* __restrict__ W1, const float* __restrict__ b1,
                const float* __restrict__ W2, const float* __restrict__ b2,
                float* __restrict__ out) {
    extern __shared__ float sm[];
    float* W1a = sm;                         // 160*64
    float* W1b = W1a + 10240;                // 160*64
    float* W2a = W1b + 10240;                // 128*64
    float* W2b = W2a + 8192;                 // 128*64
    float* AsT = W2b + 8192;                 // [KC][132]
    float* Hs  = AsT + KC * 132;             // [128][132]
    float* b1s = Hs + 128 * 132;             // 128
    float* b2s = b1s + 128;                  // 128

    const int tid = threadIdx.x;
    const int tx = tid & 15;                 // col group: cols tx*8 .. tx*8+7
    const int ty = tid >> 4;                 // row group: rows ty*4 .. ty*4+3
    const int node0 = blockIdx.x * TM;

    {   // stage weights, de-interleaved into half arrays
        const float4* w1v = reinterpret_cast<const float4*>(W1);
        float4* a1 = reinterpret_cast<float4*>(W1a);
        float4* bb1 = reinterpret_cast<float4*>(W1b);
#pragma unroll
        for (int i = 0; i < 10; i++) {
            int f = tid + i * 512;           // f = r*32 + c4, r<160, c4<32
            float4 v = w1v[f];
            int r = f >> 5, c4 = f & 31;
            if (c4 & 1) bb1[r * 16 + (c4 >> 1)] = v;
            else        a1[r * 16 + (c4 >> 1)] = v;
        }
        const float4* w2v = reinterpret_cast<const float4*>(W2);
        float4* a2 = reinterpret_cast<float4*>(W2a);
        float4* bb2 = reinterpret_cast<float4*>(W2b);
#pragma unroll
        for (int i = 0; i < 8; i++) {
            int f = tid + i * 512;
            float4 v = w2v[f];
            int r = f >> 5, c4 = f & 31;
            if (c4 & 1) bb2[r * 16 + (c4 >> 1)] = v;
            else        a2[r * 16 + (c4 >> 1)] = v;
        }
        if (tid < 128) b1s[tid] = b1[tid];
        else if (tid < 256) b2s[tid - 128] = b2[tid - 128];
    }

    // acc2[i][jp] holds output cols (2jp, 2jp+1) of row ty*4+i, packed f32x2
    unsigned long long acc2[4][4];
#pragma unroll
    for (int i = 0; i < 4; i++)
#pragma unroll
        for (int j = 0; j < 4; j++) acc2[i][j] = 0ULL;

    const float4* ctx4 = reinterpret_cast<const float4*>(g_ctx);

    for (int kc = 0; kc < 10; kc++) {        // K = 160 = 10 chunks of 16
        __syncthreads();                     // AsT reuse fence (covers staging on kc=0)
        {   // stage A-chunk transposed: AsT[k][m]; 512 threads = 128 rows * 4 quads
            int m = tid >> 2, q = tid & 3;
            int node = node0 + m;
            if (node >= N_NODES) node = N_NODES - 1;   // clamp loads; stores guarded
            int k = kc * KC + q * 4;
            float4 v = (k < EDGE_HID) ? ctx4[node * 8 + (k >> 2)]
                                      : nf4[node * 32 + ((k - EDGE_HID) >> 2)];
            float* p = AsT + (q * 4) * 132 + m;
            p[0]       = v.x;
            p[132]     = v.y;
            p[264]     = v.z;
            p[396]     = v.w;
        }
        __syncthreads();
#pragma unroll
        for (int kk = 0; kk < KC; kk++) {
            int kg = kc * KC + kk;
            float4 av = *reinterpret_cast<const float4*>(&AsT[kk * 132 + ty * 4]);
            unsigned long long a2[4] = {bcast2(av.x), bcast2(av.y),
                                        bcast2(av.z), bcast2(av.w)};
            ulonglong2 bA = *reinterpret_cast<const ulonglong2*>(&W1a[kg * 64 + tx * 4]);
            ulonglong2 bB = *reinterpret_cast<const ulonglong2*>(&W1b[kg * 64 + tx * 4]);
#pragma unroll
            for (int i = 0; i < 4; i++) {
                ffma2(acc2[i][0], a2[i], bA.x);
                ffma2(acc2[i][1], a2[i], bA.y);
                ffma2(acc2[i][2], a2[i], bB.x);
                ffma2(acc2[i][3], a2[i], bB.y);
            }
        }
    }

    // epilogue 1: bias + relu -> Hs[row][col]
    {
        float bb[8];
#pragma unroll
        for (int j = 0; j < 8; j++) bb[j] = b1s[tx * 8 + j];
#pragma unroll
        for (int i = 0; i < 4; i++) {
            float2 p0 = unpack2(acc2[i][0]);
            float2 p1 = unpack2(acc2[i][1]);
            float2 p2 = unpack2(acc2[i][2]);
            float2 p3 = unpack2(acc2[i][3]);
            float4 v0, v1;
            v0.x = fmaxf(p0.x + bb[0], 0.f);
            v0.y = fmaxf(p0.y + bb[1], 0.f);
            v0.z = fmaxf(p1.x + bb[2], 0.f);
            v0.w = fmaxf(p1.y + bb[3], 0.f);
            v1.x = fmaxf(p2.x + bb[4], 0.f);
            v1.y = fmaxf(p2.y + bb[5], 0.f);
            v1.z = fmaxf(p3.x + bb[6], 0.f);
            v1.w = fmaxf(p3.y + bb[7], 0.f);
            float* hp = &Hs[(ty * 4 + i) * 132 + tx * 8];
            reinterpret_cast<float4*>(hp)[0] = v0;
            reinterpret_cast<float4*>(hp)[1] = v1;
        }
    }
    __syncthreads();

    // GEMM2: out = relu(H @ W2 + b2)
#pragma unroll
    for (int i = 0; i < 4; i++)
#pragma unroll
        for (int j = 0; j < 4; j++) acc2[i][j] = 0ULL;

#pragma unroll 8
    for (int k = 0; k < 128; k++) {
        unsigned long long a2[4];
#pragma unroll
        for (int i = 0; i < 4; i++) a2[i] = bcast2(Hs[(ty * 4 + i) * 132 + k]);
        ulonglong2 bA = *reinterpret_cast<const ulonglong2*>(&W2a[k * 64 + tx * 4]);
        ulonglong2 bB = *reinterpret_cast<const ulonglong2*>(&W2b[k * 64 + tx * 4]);
#pragma unroll
        for (int i = 0; i < 4; i++) {
            ffma2(acc2[i][0], a2[i], bA.x);
            ffma2(acc2[i][1], a2[i], bA.y);
            ffma2(acc2[i][2], a2[i], bB.x);
            ffma2(acc2[i][3], a2[i], bB.y);
        }
    }

    {
        float bb[8];
#pragma unroll
        for (int j = 0; j < 8; j++) bb[j] = b2s[tx * 8 + j];
        int rem = N_NODES - node0;
#pragma unroll
        for (int i = 0; i < 4; i++) {
            int m = ty * 4 + i;
            if (m < rem) {
                float2 p0 = unpack2(acc2[i][0]);
                float2 p1 = unpack2(acc2[i][1]);
                float2 p2 = unpack2(acc2[i][2]);
                float2 p3 = unpack2(acc2[i][3]);
                float4 v0, v1;
                v0.x = fmaxf(p0.x + bb[0], 0.f);
                v0.y = fmaxf(p0.y + bb[1], 0.f);
                v0.z = fmaxf(p1.x + bb[2], 0.f);
                v0.w = fmaxf(p1.y + bb[3], 0.f);
                v1.x = fmaxf(p2.x + bb[4], 0.f);
                v1.y = fmaxf(p2.y + bb[5], 0.f);
                v1.z = fmaxf(p3.x + bb[6], 0.f);
                v1.w = fmaxf(p3.y + bb[7], 0.f);
                float* op = out + (node0 + m) * 128 + tx * 8;
                reinterpret_cast<float4*>(op)[0] = v0;
                reinterpret_cast<float4*>(op)[1] = v1;
            }
        }
    }
}

extern "C" void kernel_launch(void* const* d_in, const int* in_sizes, int n_in,
                              void* d_out, int out_size) {
    const float* edge_logits = (const float*)d_in[0];
    const float* edge_feats  = (const float*)d_in[1];
    const float* node_feats  = (const float*)d_in[2];
    const int*   dst         = (const int*)d_in[3];
    const float* W_et        = (const float*)d_in[4];
    const float* b_et        = (const float*)d_in[5];
    const float* W1          = (const float*)d_in[6];
    const float* b1          = (const float*)d_in[7];
    const float* W2          = (const float*)d_in[8];
    const float* b2          = (const float*)d_in[9];
    float* out = (float*)d_out;

    cudaFuncSetAttribute(mlp_kernel, cudaFuncAttributeMaxDynamicSharedMemorySize, 224512);

    zero_kernel<<<1024, 256>>>();
    edge_kernel<<<(N_EDGES * 4) / 256, 256>>>(edge_logits,
                                              (const float4*)edge_feats, dst);
    ctx_kernel<<<(N_NODES + 255) / 256, 256>>>(W_et, b_et);
    mlp_kernel<<<(N_NODES + TM - 1) / TM, 512, 224512>>>(
        (const float4*)node_feats, W1, b1, W2, b2, out);
    (void)in_sizes; (void)n_in; (void)out_size;
}

// round 7
// speedup vs baseline: 1.7387x; 1.7387x over previous
#include <cuda_runtime.h>
#include <cuda_bf16.h>
#include <cstdint>

#define N_NODES   100000
#define N_EDGES   1600000
#define EDGE_FEAT 16
#define EDGE_HID  32
#define NODE_FEAT 128
#define K_STR     168     // smem K stride (elements): 84 words/row -> conflict-free

// Scratch (allocation-free rule: __device__ globals)
__device__ float g_wsum[N_NODES * EDGE_FEAT];
__device__ float g_ssum[N_NODES];
__device__ float g_ctx [N_NODES * EDGE_HID];
// pre-split bf16 weights, [n][k] (transposed), zero-padded to K_STR
__device__ __nv_bfloat16 g_W1h[128 * K_STR];
__device__ __nv_bfloat16 g_W1l[128 * K_STR];
__device__ __nv_bfloat16 g_W2h[128 * K_STR];
__device__ __nv_bfloat16 g_W2l[128 * K_STR];

// bf16 hi/lo split of a float pair, packed bf16x2 words
__device__ __forceinline__ void split2(float a, float b, uint32_t& hi, uint32_t& lo) {
    __nv_bfloat162 h = __floats2bfloat162_rn(a, b);
    float2 hb = __bfloat1622float2(h);
    __nv_bfloat162 l = __floats2bfloat162_rn(a - hb.x, b - hb.y);
    hi = *reinterpret_cast<uint32_t*>(&h);
    lo = *reinterpret_cast<uint32_t*>(&l);
}

__device__ __forceinline__ void mma16816(float* d, const uint32_t* a,
                                         uint32_t b0, uint32_t b1) {
    asm volatile(
        "mma.sync.aligned.m16n8k16.row.col.f32.bf16.bf16.f32 "
        "{%0,%1,%2,%3}, {%4,%5,%6,%7}, {%8,%9}, {%0,%1,%2,%3};"
        : "+f"(d[0]), "+f"(d[1]), "+f"(d[2]), "+f"(d[3])
        : "r"(a[0]), "r"(a[1]), "r"(a[2]), "r"(a[3]), "r"(b0), "r"(b1));
}

// ---------------------------------------------------------------- zero scratch
__global__ void zero_kernel() {
    int i = blockIdx.x * blockDim.x + threadIdx.x;
    int stride = gridDim.x * blockDim.x;
    float4 z = make_float4(0.f, 0.f, 0.f, 0.f);
    float4* a = reinterpret_cast<float4*>(g_wsum);
    for (int idx = i; idx < N_NODES * EDGE_FEAT / 4; idx += stride) a[idx] = z;
    float4* b = reinterpret_cast<float4*>(g_ssum);
    for (int idx = i; idx < N_NODES / 4; idx += stride) b[idx] = z;
}

// ---------------------------------------------- pre-split weights to bf16 hi/lo
__global__ void wsplit_kernel(const float* __restrict__ W1,
                              const float* __restrict__ W2) {
    int i = blockIdx.x * blockDim.x + threadIdx.x;
    if (i >= 128 * K_STR) return;
    int n = i / K_STR, k = i % K_STR;
    float w1 = (k < 160) ? W1[k * 128 + n] : 0.f;
    __nv_bfloat16 h1 = __float2bfloat16_rn(w1);
    g_W1h[i] = h1;
    g_W1l[i] = __float2bfloat16_rn(w1 - __bfloat162float(h1));
    float w2 = (k < 128) ? W2[k * 128 + n] : 0.f;
    __nv_bfloat16 h2 = __float2bfloat16_rn(w2);
    g_W2h[i] = h2;
    g_W2l[i] = __float2bfloat16_rn(w2 - __bfloat162float(h2));
}

// ------------------------------------------------- edge pass: scatter ex, ex*f
__global__ void edge_kernel(const float* __restrict__ logits,
                            const float4* __restrict__ feats4,
                            const int* __restrict__ dst) {
    int t = blockIdx.x * blockDim.x + threadIdx.x;
    int e = t >> 2;
    int q = t & 3;
    if (e >= N_EDGES) return;
    int d = dst[e];
    float ex = __expf(logits[e]);
    float4 f = feats4[e * 4 + q];
    f.x *= ex; f.y *= ex; f.z *= ex; f.w *= ex;
    float* p = g_wsum + d * EDGE_FEAT + q * 4;
    asm volatile("red.global.add.v4.f32 [%0], {%1,%2,%3,%4};"
                 :: "l"(p), "f"(f.x), "f"(f.y), "f"(f.z), "f"(f.w) : "memory");
    if (q == 0)
        asm volatile("red.global.add.f32 [%0], %1;"
                     :: "l"(g_ssum + d), "f"(ex) : "memory");
}

// --------------------------------- per-node: normalize, 16->32 GEMM, bias, elu
__global__ void ctx_kernel(const float* __restrict__ W_et,
                           const float* __restrict__ b_et) {
    __shared__ float Ws[EDGE_FEAT * EDGE_HID];
    __shared__ float bs[EDGE_HID];
    for (int i = threadIdx.x; i < EDGE_FEAT * EDGE_HID; i += blockDim.x) Ws[i] = W_et[i];
    if (threadIdx.x < EDGE_HID) bs[threadIdx.x] = b_et[threadIdx.x];
    __syncthreads();
    int n = blockIdx.x * blockDim.x + threadIdx.x;
    if (n >= N_NODES) return;
    float s = g_ssum[n];
    float inv = (s > 0.f) ? (1.f / s) : 0.f;
    float ind = (s > 0.f) ? 1.f : 0.f;
    float gv[EDGE_FEAT];
    const float4* gp = reinterpret_cast<const float4*>(g_wsum + n * EDGE_FEAT);
#pragma unroll
    for (int k4 = 0; k4 < 4; k4++) {
        float4 v = gp[k4];
        gv[k4 * 4 + 0] = v.x * inv; gv[k4 * 4 + 1] = v.y * inv;
        gv[k4 * 4 + 2] = v.z * inv; gv[k4 * 4 + 3] = v.w * inv;
    }
    float c[EDGE_HID];
#pragma unroll
    for (int j = 0; j < EDGE_HID; j++) c[j] = ind * bs[j];
#pragma unroll
    for (int k = 0; k < EDGE_FEAT; k++) {
        float a = gv[k];
#pragma unroll
        for (int j = 0; j < EDGE_HID; j++) c[j] = fmaf(a, Ws[k * EDGE_HID + j], c[j]);
    }
    float4* outp = reinterpret_cast<float4*>(g_ctx + n * EDGE_HID);
#pragma unroll
    for (int j4 = 0; j4 < 8; j4++) {
        float4 v;
        float x;
        x = c[j4 * 4 + 0]; v.x = (x > 0.f) ? x : expm1f(x);
        x = c[j4 * 4 + 1]; v.y = (x > 0.f) ? x : expm1f(x);
        x = c[j4 * 4 + 2]; v.z = (x > 0.f) ? x : expm1f(x);
        x = c[j4 * 4 + 3]; v.w = (x > 0.f) ? x : expm1f(x);
        outp[j4] = v;
    }
}

// ---------------------------------------------------------------- fused MLP
// mma.sync (HMMA) bf16 hi/lo split: C = AhBh + AhBl + AlBh.
// 256 threads, tile 128 nodes x 128 cols; warps 2(M) x 4(N), each 64x32.
// All tiles smem-resident: Ah|Al|Bh|Bl = 4 x 128*168*2B = 168KB + biases.
template<int KSTEPS>
__device__ __forceinline__ void gemm_acc(const __nv_bfloat16* __restrict__ As,
                                         const __nv_bfloat16* __restrict__ Bs,
                                         int wm, int wn, int g, int tg,
                                         float acc[4][4][4]) {
#pragma unroll 2
    for (int ks = 0; ks < KSTEPS; ks++) {
        uint32_t a[4][4];
#pragma unroll
        for (int mf = 0; mf < 4; mf++) {
            const __nv_bfloat16* p = As + (wm * 64 + mf * 16 + g) * K_STR + ks * 16 + 2 * tg;
            a[mf][0] = *reinterpret_cast<const uint32_t*>(p);
            a[mf][1] = *reinterpret_cast<const uint32_t*>(p + 8 * K_STR);
            a[mf][2] = *reinterpret_cast<const uint32_t*>(p + 8);
            a[mf][3] = *reinterpret_cast<const uint32_t*>(p + 8 * K_STR + 8);
        }
#pragma unroll
        for (int nf = 0; nf < 4; nf++) {
            const __nv_bfloat16* q = Bs + (wn * 32 + nf * 8 + g) * K_STR + ks * 16 + 2 * tg;
            uint32_t b0 = *reinterpret_cast<const uint32_t*>(q);
            uint32_t b1 = *reinterpret_cast<const uint32_t*>(q + 8);
#pragma unroll
            for (int mf = 0; mf < 4; mf++)
                mma16816(acc[mf][nf], a[mf], b0, b1);
        }
    }
}

#define SMEM_BYTES (4 * 128 * K_STR * 2 + 1024)   // 173056

__global__ __launch_bounds__(256, 1)
void mlp_kernel(const float* __restrict__ nf,
                const float* __restrict__ b1, const float* __restrict__ b2,
                float* __restrict__ out) {
    extern __shared__ char smem[];
    __nv_bfloat16* Ah = reinterpret_cast<__nv_bfloat16*>(smem);
    __nv_bfloat16* Al = Ah + 128 * K_STR;
    __nv_bfloat16* Bh = Al + 128 * K_STR;
    __nv_bfloat16* Bl = Bh + 128 * K_STR;
    float* b1s = reinterpret_cast<float*>(Bl + 128 * K_STR);
    float* b2s = b1s + 128;

    const int tid = threadIdx.x;
    const int wid = tid >> 5, lid = tid & 31;
    const int wm = wid >> 2, wn = wid & 3;     // warp tile: rows wm*64, cols wn*32
    const int g = lid >> 2, tg = lid & 3;      // mma lane mapping
    const int node0 = blockIdx.x * 128;

    if (tid < 128) { b1s[tid] = b1[tid]; b2s[tid] = b2[tid]; }

    {   // stage B1 = pre-split W1^T
        const uint4* sh = reinterpret_cast<const uint4*>(g_W1h);
        const uint4* sl = reinterpret_cast<const uint4*>(g_W1l);
        uint4* dh = reinterpret_cast<uint4*>(Bh);
        uint4* dl = reinterpret_cast<uint4*>(Bl);
#pragma unroll
        for (int i = tid; i < 128 * K_STR / 8; i += 256) { dh[i] = sh[i]; dl[i] = sl[i]; }
    }
    {   // stage A = [ctx | nf] hi/lo split
        const float4* ctx4 = reinterpret_cast<const float4*>(g_ctx);
        const float4* nf4  = reinterpret_cast<const float4*>(nf);
        int row = tid >> 1, half = tid & 1;
        int node = node0 + row;
        if (node >= N_NODES) node = N_NODES - 1;   // clamp; output stores guarded
#pragma unroll
        for (int j = 0; j < 20; j++) {
            int k = half * 80 + j * 4;
            float4 v = (k < EDGE_HID) ? ctx4[node * 8 + (k >> 2)]
                                      : nf4[node * 32 + ((k - EDGE_HID) >> 2)];
            uint32_t h0, l0, h1, l1;
            split2(v.x, v.y, h0, l0);
            split2(v.z, v.w, h1, l1);
            *reinterpret_cast<uint2*>(&Ah[row * K_STR + k]) = make_uint2(h0, h1);
            *reinterpret_cast<uint2*>(&Al[row * K_STR + k]) = make_uint2(l0, l1);
        }
    }
    __syncthreads();

    float acc[4][4][4];
#pragma unroll
    for (int a = 0; a < 4; a++)
#pragma unroll
        for (int b = 0; b < 4; b++)
#pragma unroll
            for (int c = 0; c < 4; c++) acc[a][b][c] = 0.f;

    // GEMM1: K=160 (10 k-steps), 3 split passes
    gemm_acc<10>(Ah, Bh, wm, wn, g, tg, acc);
    gemm_acc<10>(Ah, Bl, wm, wn, g, tg, acc);
    gemm_acc<10>(Al, Bh, wm, wn, g, tg, acc);
    __syncthreads();   // everyone done reading A/B tiles

    // epilogue 1: bias+relu, hi/lo re-split -> H into Ah/Al ([m][n] as new [m][k])
#pragma unroll
    for (int mf = 0; mf < 4; mf++) {
#pragma unroll
        for (int nf = 0; nf < 4; nf++) {
            int n = wn * 32 + nf * 8 + 2 * tg;
            int m = wm * 64 + mf * 16 + g;
            float x0 = fmaxf(acc[mf][nf][0] + b1s[n],     0.f);
            float x1 = fmaxf(acc[mf][nf][1] + b1s[n + 1], 0.f);
            uint32_t h, l;
            split2(x0, x1, h, l);
            *reinterpret_cast<uint32_t*>(&Ah[m * K_STR + n]) = h;
            *reinterpret_cast<uint32_t*>(&Al[m * K_STR + n]) = l;
            float x2 = fmaxf(acc[mf][nf][2] + b1s[n],     0.f);
            float x3 = fmaxf(acc[mf][nf][3] + b1s[n + 1], 0.f);
            split2(x2, x3, h, l);
            *reinterpret_cast<uint32_t*>(&Ah[(m + 8) * K_STR + n]) = h;
            *reinterpret_cast<uint32_t*>(&Al[(m + 8) * K_STR + n]) = l;
        }
    }
    {   // stage B2 = pre-split W2^T (overwrites B1 region)
        const uint4* sh = reinterpret_cast<const uint4*>(g_W2h);
        const uint4* sl = reinterpret_cast<const uint4*>(g_W2l);
        uint4* dh = reinterpret_cast<uint4*>(Bh);
        uint4* dl = reinterpret_cast<uint4*>(Bl);
#pragma unroll
        for (int i = tid; i < 128 * K_STR / 8; i += 256) { dh[i] = sh[i]; dl[i] = sl[i]; }
    }
    __syncthreads();

#pragma unroll
    for (int a = 0; a < 4; a++)
#pragma unroll
        for (int b = 0; b < 4; b++)
#pragma unroll
            for (int c = 0; c < 4; c++) acc[a][b][c] = 0.f;

    // GEMM2: K=128 (8 k-steps), 3 split passes
    gemm_acc<8>(Ah, Bh, wm, wn, g, tg, acc);
    gemm_acc<8>(Ah, Bl, wm, wn, g, tg, acc);
    gemm_acc<8>(Al, Bh, wm, wn, g, tg, acc);

    // epilogue 2: bias+relu -> out
#pragma unroll
    for (int mf = 0; mf < 4; mf++) {
#pragma unroll
        for (int nf = 0; nf < 4; nf++) {
            int n = wn * 32 + nf * 8 + 2 * tg;
            int m = node0 + wm * 64 + mf * 16 + g;
            if (m < N_NODES) {
                float2 v;
                v.x = fmaxf(acc[mf][nf][0] + b2s[n],     0.f);
                v.y = fmaxf(acc[mf][nf][1] + b2s[n + 1], 0.f);
                *reinterpret_cast<float2*>(&out[m * 128 + n]) = v;
            }
            if (m + 8 < N_NODES) {
                float2 v;
                v.x = fmaxf(acc[mf][nf][2] + b2s[n],     0.f);
                v.y = fmaxf(acc[mf][nf][3] + b2s[n + 1], 0.f);
                *reinterpret_cast<float2*>(&out[(m + 8) * 128 + n]) = v;
            }
        }
    }
}

extern "C" void kernel_launch(void* const* d_in, const int* in_sizes, int n_in,
                              void* d_out, int out_size) {
    const float* edge_logits = (const float*)d_in[0];
    const float* edge_feats  = (const float*)d_in[1];
    const float* node_feats  = (const float*)d_in[2];
    const int*   dst         = (const int*)d_in[3];
    const float* W_et        = (const float*)d_in[4];
    const float* b_et        = (const float*)d_in[5];
    const float* W1          = (const float*)d_in[6];
    const float* b1          = (const float*)d_in[7];
    const float* W2          = (const float*)d_in[8];
    const float* b2          = (const float*)d_in[9];
    float* out = (float*)d_out;

    cudaFuncSetAttribute(mlp_kernel, cudaFuncAttributeMaxDynamicSharedMemorySize,
                         SMEM_BYTES);

    zero_kernel<<<1024, 256>>>();
    wsplit_kernel<<<(128 * K_STR + 255) / 256, 256>>>(W1, W2);
    edge_kernel<<<(N_EDGES * 4) / 256, 256>>>(edge_logits,
                                              (const float4*)edge_feats, dst);
    ctx_kernel<<<(N_NODES + 255) / 256, 256>>>(W_et, b_et);
    mlp_kernel<<<(N_NODES + 127) / 128, 256, SMEM_BYTES>>>(
        node_feats, b1, b2, out);
    (void)in_sizes; (void)n_in; (void)out_size;
}

// round 8
// speedup vs baseline: 1.8854x; 1.0844x over previous
#include <cuda_runtime.h>
#include <cuda_bf16.h>
#include <cstdint>

#define N_NODES   100000
#define N_EDGES   1600000
#define EDGE_FEAT 16
#define EDGE_HID  32
#define NODE_FEAT 128
#define K_STR     168     // smem K stride (elem): 84 words/row, conflict-free ldmatrix

// Scratch (allocation-free rule: __device__ globals)
__device__ float g_wsum[N_NODES * EDGE_FEAT];
__device__ float g_ssum[N_NODES];
// pre-split bf16 weights, [n][k] (transposed), zero-padded to K_STR
__device__ __nv_bfloat16 g_W1h[128 * K_STR];
__device__ __nv_bfloat16 g_W1l[128 * K_STR];
__device__ __nv_bfloat16 g_W2h[128 * K_STR];
__device__ __nv_bfloat16 g_W2l[128 * K_STR];

__device__ __forceinline__ uint32_t sm32(const void* p) {
    return (uint32_t)__cvta_generic_to_shared(p);
}
__device__ __forceinline__ void split2(float a, float b, uint32_t& hi, uint32_t& lo) {
    __nv_bfloat162 h = __floats2bfloat162_rn(a, b);
    float2 hb = __bfloat1622float2(h);
    __nv_bfloat162 l = __floats2bfloat162_rn(a - hb.x, b - hb.y);
    hi = *reinterpret_cast<uint32_t*>(&h);
    lo = *reinterpret_cast<uint32_t*>(&l);
}
__device__ __forceinline__ void mma16816(float* d, const uint32_t* a,
                                         uint32_t b0, uint32_t b1) {
    asm volatile(
        "mma.sync.aligned.m16n8k16.row.col.f32.bf16.bf16.f32 "
        "{%0,%1,%2,%3}, {%4,%5,%6,%7}, {%8,%9}, {%0,%1,%2,%3};"
        : "+f"(d[0]), "+f"(d[1]), "+f"(d[2]), "+f"(d[3])
        : "r"(a[0]), "r"(a[1]), "r"(a[2]), "r"(a[3]), "r"(b0), "r"(b1));
}
__device__ __forceinline__ void ldm4(uint32_t* r, uint32_t addr) {
    asm volatile("ldmatrix.sync.aligned.m8n8.x4.shared.b16 {%0,%1,%2,%3}, [%4];"
                 : "=r"(r[0]), "=r"(r[1]), "=r"(r[2]), "=r"(r[3]) : "r"(addr));
}
__device__ __forceinline__ void cp16(uint32_t dst, const void* src) {
    asm volatile("cp.async.cg.shared.global [%0], [%1], 16;"
                 :: "r"(dst), "l"(src));
}
#define CP_COMMIT() asm volatile("cp.async.commit_group;" ::: "memory")
#define CP_WAIT0()  asm volatile("cp.async.wait_group 0;" ::: "memory")

// ---------------------------------------------------------------- zero scratch
__global__ void zero_kernel() {
    int i = blockIdx.x * blockDim.x + threadIdx.x;
    int stride = gridDim.x * blockDim.x;
    float4 z = make_float4(0.f, 0.f, 0.f, 0.f);
    float4* a = reinterpret_cast<float4*>(g_wsum);
    for (int idx = i; idx < N_NODES * EDGE_FEAT / 4; idx += stride) a[idx] = z;
    float4* b = reinterpret_cast<float4*>(g_ssum);
    for (int idx = i; idx < N_NODES / 4; idx += stride) b[idx] = z;
}

// ---------------------------------------------- pre-split weights to bf16 hi/lo
__global__ void wsplit_kernel(const float* __restrict__ W1,
                              const float* __restrict__ W2) {
    int i = blockIdx.x * blockDim.x + threadIdx.x;
    if (i >= 128 * K_STR) return;
    int n = i / K_STR, k = i % K_STR;
    float w1 = (k < 160) ? W1[k * 128 + n] : 0.f;
    __nv_bfloat16 h1 = __float2bfloat16_rn(w1);
    g_W1h[i] = h1;
    g_W1l[i] = __float2bfloat16_rn(w1 - __bfloat162float(h1));
    float w2 = (k < 128) ? W2[k * 128 + n] : 0.f;
    __nv_bfloat16 h2 = __float2bfloat16_rn(w2);
    g_W2h[i] = h2;
    g_W2l[i] = __float2bfloat16_rn(w2 - __bfloat162float(h2));
}

// ------------------------------------------------- edge pass: scatter ex, ex*f
__global__ void edge_kernel(const float* __restrict__ logits,
                            const float4* __restrict__ feats4,
                            const int* __restrict__ dst) {
    int t = blockIdx.x * blockDim.x + threadIdx.x;
    int e = t >> 2;
    int q = t & 3;
    if (e >= N_EDGES) return;
    int d = dst[e];
    float ex = __expf(logits[e]);
    float4 f = feats4[e * 4 + q];
    f.x *= ex; f.y *= ex; f.z *= ex; f.w *= ex;
    float* p = g_wsum + d * EDGE_FEAT + q * 4;
    asm volatile("red.global.add.v4.f32 [%0], {%1,%2,%3,%4};"
                 :: "l"(p), "f"(f.x), "f"(f.y), "f"(f.z), "f"(f.w) : "memory");
    if (q == 0)
        asm volatile("red.global.add.f32 [%0], %1;"
                     :: "l"(g_ssum + d), "f"(ex) : "memory");
}

// ---------------------------------------------------------------- fused MLP
// HMMA bf16 hi/lo split (AhBh+AhBl+AlBh), ldmatrix fragments, cp.async weights,
// ctx (wsum -> @W_et + b_et -> elu) computed inline during A staging.
template<int KSTEPS>
__device__ __forceinline__ void gemm_acc(uint32_t aBase, uint32_t bBase,
                                         int lid, int wm, int wn,
                                         float acc[4][4][4]) {
    const uint32_t aOff = ((wm * 64 + (lid & 15)) * K_STR + 8 * (lid >> 4)) * 2;
    const uint32_t bOff = ((wn * 32 + ((lid >> 4) << 3) + (lid & 7)) * K_STR
                           + 8 * ((lid >> 3) & 1)) * 2;
#pragma unroll 2
    for (int ks = 0; ks < KSTEPS; ks++) {
        uint32_t a[4][4];
#pragma unroll
        for (int mf = 0; mf < 4; mf++)
            ldm4(a[mf], aBase + aOff + mf * 16 * K_STR * 2 + ks * 32);
        uint32_t b[2][4];
        ldm4(b[0], bBase + bOff + ks * 32);
        ldm4(b[1], bBase + bOff + 16 * K_STR * 2 + ks * 32);
#pragma unroll
        for (int p = 0; p < 2; p++)
#pragma unroll
            for (int h = 0; h < 2; h++)
#pragma unroll
                for (int mf = 0; mf < 4; mf++)
                    mma16816(acc[mf][p * 2 + h], a[mf], b[p][2 * h], b[p][2 * h + 1]);
    }
}

#define SMEM_BYTES (4 * 128 * K_STR * 2 + 3200)   // 175232

__global__ __launch_bounds__(256, 1)
void mlp_kernel(const float* __restrict__ nf,
                const float* __restrict__ W_et, const float* __restrict__ b_et,
                const float* __restrict__ b1, const float* __restrict__ b2,
                float* __restrict__ out) {
    extern __shared__ char smem[];
    __nv_bfloat16* Ah = reinterpret_cast<__nv_bfloat16*>(smem);
    __nv_bfloat16* Al = Ah + 128 * K_STR;
    __nv_bfloat16* Bh = Al + 128 * K_STR;
    __nv_bfloat16* Bl = Bh + 128 * K_STR;
    float* b1s  = reinterpret_cast<float*>(Bl + 128 * K_STR);
    float* b2s  = b1s + 128;
    float* Wets = b2s + 128;          // [16][32]
    float* bets = Wets + 512;         // [32]

    const int tid = threadIdx.x;
    const int wid = tid >> 5, lid = tid & 31;
    const int wm = wid >> 2, wn = wid & 3;
    const int g = lid >> 2, tg = lid & 3;
    const int node0 = blockIdx.x * 128;
    const uint32_t ahA = sm32(Ah), alA = sm32(Al), bhA = sm32(Bh), blA = sm32(Bl);

    {   // B1 weights via cp.async (overlaps everything below)
        const char* s1h = reinterpret_cast<const char*>(g_W1h);
        const char* s1l = reinterpret_cast<const char*>(g_W1l);
#pragma unroll
        for (int i = tid; i < 2688; i += 256) {
            cp16(bhA + i * 16, s1h + i * 16);
            cp16(blA + i * 16, s1l + i * 16);
        }
        CP_COMMIT();
    }
    // biases + W_et to smem
    if (tid < 128) { b1s[tid] = b1[tid]; b2s[tid] = b2[tid]; }
    for (int i = tid; i < 512; i += 256) Wets[i] = W_et[i];
    if (tid < 32) bets[tid] = b_et[tid];
    __syncthreads();   // Wets/bets visible before ctx math

    {   // A staging: ctx inline + node_feats, hi/lo split
        int row = tid >> 1, half = tid & 1;
        int node = node0 + row;
        if (node >= N_NODES) node = N_NODES - 1;   // clamp; out stores guarded
        float s = g_ssum[node];
        float inv = (s > 0.f) ? (1.f / s) : 0.f;
        float ind = (s > 0.f) ? 1.f : 0.f;
        float gv[16];
        const float4* gp = reinterpret_cast<const float4*>(g_wsum + node * 16);
#pragma unroll
        for (int k4 = 0; k4 < 4; k4++) {
            float4 v = gp[k4];
            gv[k4 * 4 + 0] = v.x * inv; gv[k4 * 4 + 1] = v.y * inv;
            gv[k4 * 4 + 2] = v.z * inv; gv[k4 * 4 + 3] = v.w * inv;
        }
        // this thread's 16 ctx columns: j in [16*half, 16*half+16)
        float c[16];
        const int j0 = 16 * half;
#pragma unroll
        for (int j = 0; j < 16; j++) c[j] = ind * bets[j0 + j];
#pragma unroll
        for (int k = 0; k < 16; k++) {
            float a = gv[k];
#pragma unroll
            for (int j = 0; j < 16; j++) c[j] = fmaf(a, Wets[k * 32 + j0 + j], c[j]);
        }
#pragma unroll
        for (int j = 0; j < 16; j++) c[j] = (c[j] > 0.f) ? c[j] : expm1f(c[j]);
#pragma unroll
        for (int t = 0; t < 4; t++) {
            uint32_t h0, l0, h1, l1;
            split2(c[4 * t], c[4 * t + 1], h0, l0);
            split2(c[4 * t + 2], c[4 * t + 3], h1, l1);
            *reinterpret_cast<uint2*>(&Ah[row * K_STR + j0 + 4 * t]) = make_uint2(h0, h1);
            *reinterpret_cast<uint2*>(&Al[row * K_STR + j0 + 4 * t]) = make_uint2(l0, l1);
        }
        // node_feats: half 0 -> k in [32,96), half 1 -> [96,160)
        const float4* nf4 = reinterpret_cast<const float4*>(nf);
        int kb = 32 + 64 * half;
#pragma unroll
        for (int j = 0; j < 16; j++) {
            int k = kb + 4 * j;
            float4 v = nf4[node * 32 + ((k - 32) >> 2)];
            uint32_t h0, l0, h1, l1;
            split2(v.x, v.y, h0, l0);
            split2(v.z, v.w, h1, l1);
            *reinterpret_cast<uint2*>(&Ah[row * K_STR + k]) = make_uint2(h0, h1);
            *reinterpret_cast<uint2*>(&Al[row * K_STR + k]) = make_uint2(l0, l1);
        }
    }
    CP_WAIT0();
    __syncthreads();

    float acc[4][4][4];
#pragma unroll
    for (int a = 0; a < 4; a++)
#pragma unroll
        for (int b = 0; b < 4; b++)
#pragma unroll
            for (int c = 0; c < 4; c++) acc[a][b][c] = 0.f;

    // GEMM1: K=160 (10 k-steps), 3 split passes
    gemm_acc<10>(ahA, bhA, lid, wm, wn, acc);
    gemm_acc<10>(ahA, blA, lid, wm, wn, acc);
    gemm_acc<10>(alA, bhA, lid, wm, wn, acc);
    __syncthreads();   // done reading A/B tiles

    {   // B2 weights via cp.async — overlaps epilogue-1 math below
        const char* s2h = reinterpret_cast<const char*>(g_W2h);
        const char* s2l = reinterpret_cast<const char*>(g_W2l);
#pragma unroll
        for (int i = tid; i < 2688; i += 256) {
            cp16(bhA + i * 16, s2h + i * 16);
            cp16(blA + i * 16, s2l + i * 16);
        }
        CP_COMMIT();
    }

    // epilogue 1: bias+relu, re-split H -> Ah/Al ([m][n] as new [m][k])
#pragma unroll
    for (int mf = 0; mf < 4; mf++) {
#pragma unroll
        for (int nfi = 0; nfi < 4; nfi++) {
            int n = wn * 32 + nfi * 8 + 2 * tg;
            int m = wm * 64 + mf * 16 + g;
            float x0 = fmaxf(acc[mf][nfi][0] + b1s[n],     0.f);
            float x1 = fmaxf(acc[mf][nfi][1] + b1s[n + 1], 0.f);
            uint32_t h, l;
            split2(x0, x1, h, l);
            *reinterpret_cast<uint32_t*>(&Ah[m * K_STR + n]) = h;
            *reinterpret_cast<uint32_t*>(&Al[m * K_STR + n]) = l;
            float x2 = fmaxf(acc[mf][nfi][2] + b1s[n],     0.f);
            float x3 = fmaxf(acc[mf][nfi][3] + b1s[n + 1], 0.f);
            split2(x2, x3, h, l);
            *reinterpret_cast<uint32_t*>(&Ah[(m + 8) * K_STR + n]) = h;
            *reinterpret_cast<uint32_t*>(&Al[(m + 8) * K_STR + n]) = l;
        }
    }
    CP_WAIT0();
    __syncthreads();

#pragma unroll
    for (int a = 0; a < 4; a++)
#pragma unroll
        for (int b = 0; b < 4; b++)
#pragma unroll
            for (int c = 0; c < 4; c++) acc[a][b][c] = 0.f;

    // GEMM2: K=128 (8 k-steps), 3 split passes
    gemm_acc<8>(ahA, bhA, lid, wm, wn, acc);
    gemm_acc<8>(ahA, blA, lid, wm, wn, acc);
    gemm_acc<8>(alA, bhA, lid, wm, wn, acc);

    // epilogue 2: bias+relu -> out
#pragma unroll
    for (int mf = 0; mf < 4; mf++) {
#pragma unroll
        for (int nfi = 0; nfi < 4; nfi++) {
            int n = wn * 32 + nfi * 8 + 2 * tg;
            int m = node0 + wm * 64 + mf * 16 + g;
            if (m < N_NODES) {
                float2 v;
                v.x = fmaxf(acc[mf][nfi][0] + b2s[n],     0.f);
                v.y = fmaxf(acc[mf][nfi][1] + b2s[n + 1], 0.f);
                *reinterpret_cast<float2*>(&out[m * 128 + n]) = v;
            }
            if (m + 8 < N_NODES) {
                float2 v;
                v.x = fmaxf(acc[mf][nfi][2] + b2s[n],     0.f);
                v.y = fmaxf(acc[mf][nfi][3] + b2s[n + 1], 0.f);
                *reinterpret_cast<float2*>(&out[(m + 8) * 128 + n]) = v;
            }
        }
    }
}

extern "C" void kernel_launch(void* const* d_in, const int* in_sizes, int n_in,
                              void* d_out, int out_size) {
    const float* edge_logits = (const float*)d_in[0];
    const float* edge_feats  = (const float*)d_in[1];
    const float* node_feats  = (const float*)d_in[2];
    const int*   dst         = (const int*)d_in[3];
    const float* W_et        = (const float*)d_in[4];
    const float* b_et        = (const float*)d_in[5];
    const float* W1          = (const float*)d_in[6];
    const float* b1          = (const float*)d_in[7];
    const float* W2          = (const float*)d_in[8];
    const float* b2          = (const float*)d_in[9];
    float* out = (float*)d_out;

    cudaFuncSetAttribute(mlp_kernel, cudaFuncAttributeMaxDynamicSharedMemorySize,
                         SMEM_BYTES);

    zero_kernel<<<1024, 256>>>();
    wsplit_kernel<<<(128 * K_STR + 255) / 256, 256>>>(W1, W2);
    edge_kernel<<<(N_EDGES * 4) / 256, 256>>>(edge_logits,
                                              (const float4*)edge_feats, dst);
    mlp_kernel<<<(N_NODES + 127) / 128, 256, SMEM_BYTES>>>(
        node_feats, W_et, b_et, b1, b2, out);
    (void)in_sizes; (void)n_in; (void)out_size;
}

// round 10
// speedup vs baseline: 1.9071x; 1.0115x over previous
#include <cuda_runtime.h>
#include <cuda_bf16.h>
#include <cstdint>

#define N_NODES   100000
#define N_EDGES   1600000
#define EDGE_FEAT 16
#define EDGE_HID  32
#define NODE_FEAT 128
#define K_STR     168     // smem K stride (elem): 84 words/row, conflict-free ldmatrix

// Scratch (allocation-free rule: __device__ globals)
__device__ float g_wsum[N_NODES * EDGE_FEAT];
__device__ float g_ssum[N_NODES];
// pre-split bf16 weights, [n][k] (transposed), zero-padded to K_STR
__device__ __nv_bfloat16 g_W1h[128 * K_STR];
__device__ __nv_bfloat16 g_W1l[128 * K_STR];
__device__ __nv_bfloat16 g_W2h[128 * K_STR];
__device__ __nv_bfloat16 g_W2l[128 * K_STR];

__device__ __forceinline__ uint32_t sm32(const void* p) {
    return (uint32_t)__cvta_generic_to_shared(p);
}
__device__ __forceinline__ void split2(float a, float b, uint32_t& hi, uint32_t& lo) {
    __nv_bfloat162 h = __floats2bfloat162_rn(a, b);
    float2 hb = __bfloat1622float2(h);
    __nv_bfloat162 l = __floats2bfloat162_rn(a - hb.x, b - hb.y);
    hi = *reinterpret_cast<uint32_t*>(&h);
    lo = *reinterpret_cast<uint32_t*>(&l);
}
__device__ __forceinline__ void mma16816(float* d, const uint32_t* a,
                                         uint32_t b0, uint32_t b1) {
    asm volatile(
        "mma.sync.aligned.m16n8k16.row.col.f32.bf16.bf16.f32 "
        "{%0,%1,%2,%3}, {%4,%5,%6,%7}, {%8,%9}, {%0,%1,%2,%3};"
        : "+f"(d[0]), "+f"(d[1]), "+f"(d[2]), "+f"(d[3])
        : "r"(a[0]), "r"(a[1]), "r"(a[2]), "r"(a[3]), "r"(b0), "r"(b1));
}
__device__ __forceinline__ void ldm4(uint32_t* r, uint32_t addr) {
    asm volatile("ldmatrix.sync.aligned.m8n8.x4.shared.b16 {%0,%1,%2,%3}, [%4];"
                 : "=r"(r[0]), "=r"(r[1]), "=r"(r[2]), "=r"(r[3]) : "r"(addr));
}
__device__ __forceinline__ void cp16(uint32_t dst, const void* src) {
    asm volatile("cp.async.cg.shared.global [%0], [%1], 16;"
                 :: "r"(dst), "l"(src));
}
#define CP_COMMIT() asm volatile("cp.async.commit_group;" ::: "memory")
#define CP_WAIT0()  asm volatile("cp.async.wait_group 0;" ::: "memory")

// ---------------------------------------------------------------- zero scratch
__global__ void zero_kernel() {
    int i = blockIdx.x * blockDim.x + threadIdx.x;
    int stride = gridDim.x * blockDim.x;
    float4 z = make_float4(0.f, 0.f, 0.f, 0.f);
    float4* a = reinterpret_cast<float4*>(g_wsum);
    for (int idx = i; idx < N_NODES * EDGE_FEAT / 4; idx += stride) a[idx] = z;
    float4* b = reinterpret_cast<float4*>(g_ssum);
    for (int idx = i; idx < N_NODES / 4; idx += stride) b[idx] = z;
}

// ---------------------------------------------- pre-split weights to bf16 hi/lo
__global__ void wsplit_kernel(const float* __restrict__ W1,
                              const float* __restrict__ W2) {
    int i = blockIdx.x * blockDim.x + threadIdx.x;
    if (i >= 128 * K_STR) return;
    int n = i / K_STR, k = i % K_STR;
    float w1 = (k < 160) ? W1[k * 128 + n] : 0.f;
    __nv_bfloat16 h1 = __float2bfloat16_rn(w1);
    g_W1h[i] = h1;
    g_W1l[i] = __float2bfloat16_rn(w1 - __bfloat162float(h1));
    float w2 = (k < 128) ? W2[k * 128 + n] : 0.f;
    __nv_bfloat16 h2 = __float2bfloat16_rn(w2);
    g_W2h[i] = h2;
    g_W2l[i] = __float2bfloat16_rn(w2 - __bfloat162float(h2));
}

// ------------------------------------------------- edge pass: scatter ex, ex*f
__global__ void edge_kernel(const float* __restrict__ logits,
                            const float4* __restrict__ feats4,
                            const int* __restrict__ dst) {
    int t = blockIdx.x * blockDim.x + threadIdx.x;
    int e = t >> 2;
    int q = t & 3;
    if (e >= N_EDGES) return;
    int d = dst[e];
    float ex = __expf(logits[e]);
    float4 f = feats4[e * 4 + q];
    f.x *= ex; f.y *= ex; f.z *= ex; f.w *= ex;
    float* p = g_wsum + d * EDGE_FEAT + q * 4;
    asm volatile("red.global.add.v4.f32 [%0], {%1,%2,%3,%4};"
                 :: "l"(p), "f"(f.x), "f"(f.y), "f"(f.z), "f"(f.w) : "memory");
    if (q == 0)
        asm volatile("red.global.add.f32 [%0], %1;"
                     :: "l"(g_ssum + d), "f"(ex) : "memory");
}

// ---------------------------------------------------------------- fused MLP
// HMMA bf16 hi/lo split (AhBh+AhBl+AlBh). 512 threads, 4x4 warp grid,
// 32x32 warp tiles. ldmatrix fragments, cp.async weights, ctx inline.
template<int KSTEPS>
__device__ __forceinline__ void gemm_acc(uint32_t aBase, uint32_t bBase,
                                         int lid, int wm, int wn,
                                         float acc[2][4][4]) {
    const uint32_t aOff = ((wm * 32 + (lid & 15)) * K_STR + 8 * (lid >> 4)) * 2;
    const uint32_t bOff = ((wn * 32 + ((lid >> 4) << 3) + (lid & 7)) * K_STR
                           + 8 * ((lid >> 3) & 1)) * 2;
#pragma unroll 2
    for (int ks = 0; ks < KSTEPS; ks++) {
        uint32_t a[2][4];
#pragma unroll
        for (int mf = 0; mf < 2; mf++)
            ldm4(a[mf], aBase + aOff + mf * 16 * K_STR * 2 + ks * 32);
        uint32_t b[2][4];
        ldm4(b[0], bBase + bOff + ks * 32);
        ldm4(b[1], bBase + bOff + 16 * K_STR * 2 + ks * 32);
#pragma unroll
        for (int p = 0; p < 2; p++)
#pragma unroll
            for (int h = 0; h < 2; h++)
#pragma unroll
                for (int mf = 0; mf < 2; mf++)
                    mma16816(acc[mf][p * 2 + h], a[mf], b[p][2 * h], b[p][2 * h + 1]);
    }
}

#define SMEM_BYTES (4 * 128 * K_STR * 2 + 3200)   // 175232

__global__ __launch_bounds__(512, 1)
void mlp_kernel(const float* __restrict__ nf,
                const float* __restrict__ W_et, const float* __restrict__ b_et,
                const float* __restrict__ b1, const float* __restrict__ b2,
                float* __restrict__ out) {
    extern __shared__ char smem[];
    __nv_bfloat16* Ah = reinterpret_cast<__nv_bfloat16*>(smem);
    __nv_bfloat16* Al = Ah + 128 * K_STR;
    __nv_bfloat16* Bh = Al + 128 * K_STR;
    __nv_bfloat16* Bl = Bh + 128 * K_STR;
    float* b1s  = reinterpret_cast<float*>(Bl + 128 * K_STR);
    float* b2s  = b1s + 128;
    float* Wets = b2s + 128;          // [16][32]
    float* bets = Wets + 512;         // [32]

    const int tid = threadIdx.x;
    const int wid = tid >> 5, lid = tid & 31;
    const int wm = wid >> 2, wn = wid & 3;   // 4x4 warp grid, 32x32 tiles
    const int g = lid >> 2, tg = lid & 3;
    const int node0 = blockIdx.x * 128;
    const uint32_t ahA = sm32(Ah), alA = sm32(Al), bhA = sm32(Bh), blA = sm32(Bl);

    {   // B1 weights via cp.async (overlaps staging below)
        const char* s1h = reinterpret_cast<const char*>(g_W1h);
        const char* s1l = reinterpret_cast<const char*>(g_W1l);
#pragma unroll
        for (int i = tid; i < 2688; i += 512) {
            cp16(bhA + i * 16, s1h + i * 16);
            cp16(blA + i * 16, s1l + i * 16);
        }
        CP_COMMIT();
    }
    if (tid < 128) { b1s[tid] = b1[tid]; b2s[tid] = b2[tid]; }
    if (tid < 512) Wets[tid] = W_et[tid];
    if (tid < 32) bets[tid] = b_et[tid];
    __syncthreads();   // Wets/bets visible before ctx math

    {   // A staging: 4 threads/row; ctx inline (8 cols each) + nf (32 cols each)
        int row = tid >> 2, q = tid & 3;
        int node = node0 + row;
        if (node >= N_NODES) node = N_NODES - 1;   // clamp; out stores guarded
        float s = g_ssum[node];
        float inv = (s > 0.f) ? (1.f / s) : 0.f;
        float ind = (s > 0.f) ? 1.f : 0.f;
        float gv[16];
        const float4* gp = reinterpret_cast<const float4*>(g_wsum + node * 16);
#pragma unroll
        for (int k4 = 0; k4 < 4; k4++) {
            float4 v = gp[k4];
            gv[k4 * 4 + 0] = v.x * inv; gv[k4 * 4 + 1] = v.y * inv;
            gv[k4 * 4 + 2] = v.z * inv; gv[k4 * 4 + 3] = v.w * inv;
        }
        // this thread's 8 ctx columns: [8q, 8q+8)
        float c[8];
        const int j0 = 8 * q;
#pragma unroll
        for (int j = 0; j < 8; j++) c[j] = ind * bets[j0 + j];
#pragma unroll
        for (int k = 0; k < 16; k++) {
            float a = gv[k];
#pragma unroll
            for (int j = 0; j < 8; j++) c[j] = fmaf(a, Wets[k * 32 + j0 + j], c[j]);
        }
#pragma unroll
        for (int j = 0; j < 8; j++) c[j] = (c[j] > 0.f) ? c[j] : expm1f(c[j]);
#pragma unroll
        for (int t = 0; t < 2; t++) {
            uint32_t h0, l0, h1, l1;
            split2(c[4 * t], c[4 * t + 1], h0, l0);
            split2(c[4 * t + 2], c[4 * t + 3], h1, l1);
            *reinterpret_cast<uint2*>(&Ah[row * K_STR + j0 + 4 * t]) = make_uint2(h0, h1);
            *reinterpret_cast<uint2*>(&Al[row * K_STR + j0 + 4 * t]) = make_uint2(l0, l1);
        }
        // node_feats: this thread covers k in [32+32q, 64+32q)
        const float4* nf4 = reinterpret_cast<const float4*>(nf);
        int kb = 32 + 32 * q;
#pragma unroll
        for (int j = 0; j < 8; j++) {
            int k = kb + 4 * j;
            float4 v = nf4[node * 32 + ((k - 32) >> 2)];
            uint32_t h0, l0, h1, l1;
            split2(v.x, v.y, h0, l0);
            split2(v.z, v.w, h1, l1);
            *reinterpret_cast<uint2*>(&Ah[row * K_STR + k]) = make_uint2(h0, h1);
            *reinterpret_cast<uint2*>(&Al[row * K_STR + k]) = make_uint2(l0, l1);
        }
    }
    CP_WAIT0();
    __syncthreads();

    float acc[2][4][4];
#pragma unroll
    for (int a = 0; a < 2; a++)
#pragma unroll
        for (int b = 0; b < 4; b++)
#pragma unroll
            for (int c = 0; c < 4; c++) acc[a][b][c] = 0.f;

    // GEMM1: K=160 (10 k-steps), 3 split passes
    gemm_acc<10>(ahA, bhA, lid, wm, wn, acc);
    gemm_acc<10>(ahA, blA, lid, wm, wn, acc);
    gemm_acc<10>(alA, bhA, lid, wm, wn, acc);
    __syncthreads();   // done reading A/B tiles

    {   // B2 weights via cp.async — overlaps epilogue-1 math below
        const char* s2h = reinterpret_cast<const char*>(g_W2h);
        const char* s2l = reinterpret_cast<const char*>(g_W2l);
#pragma unroll
        for (int i = tid; i < 2688; i += 512) {
            cp16(bhA + i * 16, s2h + i * 16);
            cp16(blA + i * 16, s2l + i * 16);
        }
        CP_COMMIT();
    }

    // epilogue 1: bias+relu, re-split H -> Ah/Al ([m][n] as new [m][k])
#pragma unroll
    for (int mf = 0; mf < 2; mf++) {
#pragma unroll
        for (int nfi = 0; nfi < 4; nfi++) {
            int n = wn * 32 + nfi * 8 + 2 * tg;
            int m = wm * 32 + mf * 16 + g;
            float x0 = fmaxf(acc[mf][nfi][0] + b1s[n],     0.f);
            float x1 = fmaxf(acc[mf][nfi][1] + b1s[n + 1], 0.f);
            uint32_t h, l;
            split2(x0, x1, h, l);
            *reinterpret_cast<uint32_t*>(&Ah[m * K_STR + n]) = h;
            *reinterpret_cast<uint32_t*>(&Al[m * K_STR + n]) = l;
            float x2 = fmaxf(acc[mf][nfi][2] + b1s[n],     0.f);
            float x3 = fmaxf(acc[mf][nfi][3] + b1s[n + 1], 0.f);
            split2(x2, x3, h, l);
            *reinterpret_cast<uint32_t*>(&Ah[(m + 8) * K_STR + n]) = h;
            *reinterpret_cast<uint32_t*>(&Al[(m + 8) * K_STR + n]) = l;
        }
    }
    CP_WAIT0();
    __syncthreads();

#pragma unroll
    for (int a = 0; a < 2; a++)
#pragma unroll
        for (int b = 0; b < 4; b++)
#pragma unroll
            for (int c = 0; c < 4; c++) acc[a][b][c] = 0.f;

    // GEMM2: K=128 (8 k-steps), 3 split passes
    gemm_acc<8>(ahA, bhA, lid, wm, wn, acc);
    gemm_acc<8>(ahA, blA, lid, wm, wn, acc);
    gemm_acc<8>(alA, bhA, lid, wm, wn, acc);

    // epilogue 2: bias+relu -> out
#pragma unroll
    for (int mf = 0; mf < 2; mf++) {
#pragma unroll
        for (int nfi = 0; nfi < 4; nfi++) {
            int n = wn * 32 + nfi * 8 + 2 * tg;
            int m = node0 + wm * 32 + mf * 16 + g;
            if (m < N_NODES) {
                float2 v;
                v.x = fmaxf(acc[mf][nfi][0] + b2s[n],     0.f);
                v.y = fmaxf(acc[mf][nfi][1] + b2s[n + 1], 0.f);
                *reinterpret_cast<float2*>(&out[m * 128 + n]) = v;
            }
            if (m + 8 < N_NODES) {
                float2 v;
                v.x = fmaxf(acc[mf][nfi][2] + b2s[n],     0.f);
                v.y = fmaxf(acc[mf][nfi][3] + b2s[n + 1], 0.f);
                *reinterpret_cast<float2*>(&out[(m + 8) * 128 + n]) = v;
            }
        }
    }
}

extern "C" void kernel_launch(void* const* d_in, const int* in_sizes, int n_in,
                              void* d_out, int out_size) {
    const float* edge_logits = (const float*)d_in[0];
    const float* edge_feats  = (const float*)d_in[1];
    const float* node_feats  = (const float*)d_in[2];
    const int*   dst         = (const int*)d_in[3];
    const float* W_et        = (const float*)d_in[4];
    const float* b_et        = (const float*)d_in[5];
    const float* W1          = (const float*)d_in[6];
    const float* b1          = (const float*)d_in[7];
    const float* W2          = (const float*)d_in[8];
    const float* b2          = (const float*)d_in[9];
    float* out = (float*)d_out;

    cudaFuncSetAttribute(mlp_kernel, cudaFuncAttributeMaxDynamicSharedMemorySize,
                         SMEM_BYTES);

    zero_kernel<<<1024, 256>>>();
    wsplit_kernel<<<(128 * K_STR + 255) / 256, 256>>>(W1, W2);
    edge_kernel<<<(N_EDGES * 4) / 256, 256>>>(edge_logits,
                                              (const float4*)edge_feats, dst);
    mlp_kernel<<<(N_NODES + 127) / 128, 512, SMEM_BYTES>>>(
        node_feats, W_et, b_et, b1, b2, out);
    (void)in_sizes; (void)n_in; (void)out_size;
}

// round 11
// speedup vs baseline: 1.9302x; 1.0121x over previous
#include <cuda_runtime.h>
#include <cuda_bf16.h>
#include <cstdint>

#define N_NODES   100000
#define N_EDGES   1600000
#define EDGE_FEAT 16
#define EDGE_HID  32
#define NODE_FEAT 128
#define K_STR     168     // smem K stride (elem): 84 words/row, conflict-free ldmatrix

// Scratch (allocation-free rule: __device__ globals)
__device__ float g_wsum[N_NODES * EDGE_FEAT];
__device__ float g_ssum[N_NODES];
// pre-split bf16 weights, [n][k] (transposed), zero-padded to K_STR
__device__ __nv_bfloat16 g_W1h[128 * K_STR];
__device__ __nv_bfloat16 g_W1l[128 * K_STR];
__device__ __nv_bfloat16 g_W2h[128 * K_STR];
__device__ __nv_bfloat16 g_W2l[128 * K_STR];

__device__ __forceinline__ uint32_t sm32(const void* p) {
    return (uint32_t)__cvta_generic_to_shared(p);
}
__device__ __forceinline__ void split2(float a, float b, uint32_t& hi, uint32_t& lo) {
    __nv_bfloat162 h = __floats2bfloat162_rn(a, b);
    float2 hb = __bfloat1622float2(h);
    __nv_bfloat162 l = __floats2bfloat162_rn(a - hb.x, b - hb.y);
    hi = *reinterpret_cast<uint32_t*>(&h);
    lo = *reinterpret_cast<uint32_t*>(&l);
}
__device__ __forceinline__ void mma16816(float* d, const uint32_t* a,
                                         uint32_t b0, uint32_t b1) {
    asm volatile(
        "mma.sync.aligned.m16n8k16.row.col.f32.bf16.bf16.f32 "
        "{%0,%1,%2,%3}, {%4,%5,%6,%7}, {%8,%9}, {%0,%1,%2,%3};"
        : "+f"(d[0]), "+f"(d[1]), "+f"(d[2]), "+f"(d[3])
        : "r"(a[0]), "r"(a[1]), "r"(a[2]), "r"(a[3]), "r"(b0), "r"(b1));
}
__device__ __forceinline__ void ldm4(uint32_t* r, uint32_t addr) {
    asm volatile("ldmatrix.sync.aligned.m8n8.x4.shared.b16 {%0,%1,%2,%3}, [%4];"
                 : "=r"(r[0]), "=r"(r[1]), "=r"(r[2]), "=r"(r[3]) : "r"(addr));
}
__device__ __forceinline__ void cp16(uint32_t dst, const void* src) {
    asm volatile("cp.async.cg.shared.global [%0], [%1], 16;"
                 :: "r"(dst), "l"(src));
}
#define CP_COMMIT() asm volatile("cp.async.commit_group;" ::: "memory")
#define CP_WAIT0()  asm volatile("cp.async.wait_group 0;" ::: "memory")

// ---------------------------------------------------------------- zero scratch
__global__ void zero_kernel() {
    int i = blockIdx.x * blockDim.x + threadIdx.x;
    int stride = gridDim.x * blockDim.x;
    float4 z = make_float4(0.f, 0.f, 0.f, 0.f);
    float4* a = reinterpret_cast<float4*>(g_wsum);
    for (int idx = i; idx < N_NODES * EDGE_FEAT / 4; idx += stride) a[idx] = z;
    float4* b = reinterpret_cast<float4*>(g_ssum);
    for (int idx = i; idx < N_NODES / 4; idx += stride) b[idx] = z;
}

// ---------------------------------------------- pre-split weights to bf16 hi/lo
__global__ void wsplit_kernel(const float* __restrict__ W1,
                              const float* __restrict__ W2) {
    int i = blockIdx.x * blockDim.x + threadIdx.x;
    if (i >= 128 * K_STR) return;
    int n = i / K_STR, k = i % K_STR;
    float w1 = (k < 160) ? W1[k * 128 + n] : 0.f;
    __nv_bfloat16 h1 = __float2bfloat16_rn(w1);
    g_W1h[i] = h1;
    g_W1l[i] = __float2bfloat16_rn(w1 - __bfloat162float(h1));
    float w2 = (k < 128) ? W2[k * 128 + n] : 0.f;
    __nv_bfloat16 h2 = __float2bfloat16_rn(w2);
    g_W2h[i] = h2;
    g_W2l[i] = __float2bfloat16_rn(w2 - __bfloat162float(h2));
}

// ------------------------------------------------- edge pass: scatter ex, ex*f
__global__ void edge_kernel(const float* __restrict__ logits,
                            const float4* __restrict__ feats4,
                            const int* __restrict__ dst) {
    int t = blockIdx.x * blockDim.x + threadIdx.x;
    int e = t >> 2;
    int q = t & 3;
    if (e >= N_EDGES) return;
    int d = dst[e];
    float ex = __expf(logits[e]);
    float4 f = feats4[e * 4 + q];
    f.x *= ex; f.y *= ex; f.z *= ex; f.w *= ex;
    float* p = g_wsum + d * EDGE_FEAT + q * 4;
    asm volatile("red.global.add.v4.f32 [%0], {%1,%2,%3,%4};"
                 :: "l"(p), "f"(f.x), "f"(f.y), "f"(f.z), "f"(f.w) : "memory");
    if (q == 0)
        asm volatile("red.global.add.f32 [%0], %1;"
                     :: "l"(g_ssum + d), "f"(ex) : "memory");
}

// ---------------------------------------------------------------- fused MLP
// HMMA bf16 hi/lo split, MERGED passes: per k-step load Ah/Al/Bh/Bl fragments
// once and fire 24 mma (AhBh + AhBl + AlBh into the same accumulators).
// 512 threads, 4x4 warp grid, 32x32 warp tiles.
template<int KSTEPS>
__device__ __forceinline__ void gemm_merged(uint32_t ahA, uint32_t alA,
                                            uint32_t bhA, uint32_t blA,
                                            int lid, int wm, int wn,
                                            float acc[2][4][4]) {
    const uint32_t aOff = ((wm * 32 + (lid & 15)) * K_STR + 8 * (lid >> 4)) * 2;
    const uint32_t bOff = ((wn * 32 + ((lid >> 4) << 3) + (lid & 7)) * K_STR
                           + 8 * ((lid >> 3) & 1)) * 2;
#pragma unroll 2
    for (int ks = 0; ks < KSTEPS; ks++) {
        uint32_t ah[2][4], al[2][4], bh[2][4], bl[2][4];
#pragma unroll
        for (int mf = 0; mf < 2; mf++) {
            ldm4(ah[mf], ahA + aOff + mf * 16 * K_STR * 2 + ks * 32);
            ldm4(al[mf], alA + aOff + mf * 16 * K_STR * 2 + ks * 32);
        }
#pragma unroll
        for (int pb = 0; pb < 2; pb++) {
            ldm4(bh[pb], bhA + bOff + pb * 16 * K_STR * 2 + ks * 32);
            ldm4(bl[pb], blA + bOff + pb * 16 * K_STR * 2 + ks * 32);
        }
#pragma unroll
        for (int pb = 0; pb < 2; pb++)
#pragma unroll
            for (int h = 0; h < 2; h++)
#pragma unroll
                for (int mf = 0; mf < 2; mf++) {
                    mma16816(acc[mf][pb * 2 + h], ah[mf], bh[pb][2 * h], bh[pb][2 * h + 1]);
                    mma16816(acc[mf][pb * 2 + h], ah[mf], bl[pb][2 * h], bl[pb][2 * h + 1]);
                    mma16816(acc[mf][pb * 2 + h], al[mf], bh[pb][2 * h], bh[pb][2 * h + 1]);
                }
    }
}

#define SMEM_BYTES (4 * 128 * K_STR * 2 + 3200)   // 175232

__global__ __launch_bounds__(512, 1)
void mlp_kernel(const float* __restrict__ nf,
                const float* __restrict__ W_et, const float* __restrict__ b_et,
                const float* __restrict__ b1, const float* __restrict__ b2,
                float* __restrict__ out) {
    extern __shared__ char smem[];
    __nv_bfloat16* Ah = reinterpret_cast<__nv_bfloat16*>(smem);
    __nv_bfloat16* Al = Ah + 128 * K_STR;
    __nv_bfloat16* Bh = Al + 128 * K_STR;
    __nv_bfloat16* Bl = Bh + 128 * K_STR;
    float* b1s  = reinterpret_cast<float*>(Bl + 128 * K_STR);
    float* b2s  = b1s + 128;
    float* Wets = b2s + 128;          // [16][32]
    float* bets = Wets + 512;         // [32]

    const int tid = threadIdx.x;
    const int wid = tid >> 5, lid = tid & 31;
    const int wm = wid >> 2, wn = wid & 3;   // 4x4 warp grid, 32x32 tiles
    const int g = lid >> 2, tg = lid & 3;
    const int node0 = blockIdx.x * 128;
    const uint32_t ahA = sm32(Ah), alA = sm32(Al), bhA = sm32(Bh), blA = sm32(Bl);

    {   // B1 weights via cp.async (overlaps staging below)
        const char* s1h = reinterpret_cast<const char*>(g_W1h);
        const char* s1l = reinterpret_cast<const char*>(g_W1l);
#pragma unroll
        for (int i = tid; i < 2688; i += 512) {
            cp16(bhA + i * 16, s1h + i * 16);
            cp16(blA + i * 16, s1l + i * 16);
        }
        CP_COMMIT();
    }
    if (tid < 128) { b1s[tid] = b1[tid]; b2s[tid] = b2[tid]; }
    if (tid < 512) Wets[tid] = W_et[tid];
    if (tid < 32) bets[tid] = b_et[tid];
    __syncthreads();   // Wets/bets visible before ctx math

    {   // A staging: 4 threads/row; ctx inline (8 cols each) + nf (32 cols each)
        int row = tid >> 2, q = tid & 3;
        int node = node0 + row;
        if (node >= N_NODES) node = N_NODES - 1;   // clamp; out stores guarded
        float s = g_ssum[node];
        float inv = (s > 0.f) ? (1.f / s) : 0.f;
        float ind = (s > 0.f) ? 1.f : 0.f;
        float gv[16];
        const float4* gp = reinterpret_cast<const float4*>(g_wsum + node * 16);
#pragma unroll
        for (int k4 = 0; k4 < 4; k4++) {
            float4 v = gp[k4];
            gv[k4 * 4 + 0] = v.x * inv; gv[k4 * 4 + 1] = v.y * inv;
            gv[k4 * 4 + 2] = v.z * inv; gv[k4 * 4 + 3] = v.w * inv;
        }
        // this thread's 8 ctx columns: [8q, 8q+8)
        float c[8];
        const int j0 = 8 * q;
#pragma unroll
        for (int j = 0; j < 8; j++) c[j] = ind * bets[j0 + j];
#pragma unroll
        for (int k = 0; k < 16; k++) {
            float a = gv[k];
#pragma unroll
            for (int j = 0; j < 8; j++) c[j] = fmaf(a, Wets[k * 32 + j0 + j], c[j]);
        }
#pragma unroll
        for (int j = 0; j < 8; j++) c[j] = (c[j] > 0.f) ? c[j] : (__expf(c[j]) - 1.0f);
#pragma unroll
        for (int t = 0; t < 2; t++) {
            uint32_t h0, l0, h1, l1;
            split2(c[4 * t], c[4 * t + 1], h0, l0);
            split2(c[4 * t + 2], c[4 * t + 3], h1, l1);
            *reinterpret_cast<uint2*>(&Ah[row * K_STR + j0 + 4 * t]) = make_uint2(h0, h1);
            *reinterpret_cast<uint2*>(&Al[row * K_STR + j0 + 4 * t]) = make_uint2(l0, l1);
        }
        // node_feats: this thread covers k in [32+32q, 64+32q)
        const float4* nf4 = reinterpret_cast<const float4*>(nf);
        int kb = 32 + 32 * q;
#pragma unroll
        for (int j = 0; j < 8; j++) {
            int k = kb + 4 * j;
            float4 v = nf4[node * 32 + ((k - 32) >> 2)];
            uint32_t h0, l0, h1, l1;
            split2(v.x, v.y, h0, l0);
            split2(v.z, v.w, h1, l1);
            *reinterpret_cast<uint2*>(&Ah[row * K_STR + k]) = make_uint2(h0, h1);
            *reinterpret_cast<uint2*>(&Al[row * K_STR + k]) = make_uint2(l0, l1);
        }
    }
    CP_WAIT0();
    __syncthreads();

    float acc[2][4][4];
#pragma unroll
    for (int a = 0; a < 2; a++)
#pragma unroll
        for (int b = 0; b < 4; b++)
#pragma unroll
            for (int c = 0; c < 4; c++) acc[a][b][c] = 0.f;

    // GEMM1: K=160 (10 k-steps), merged 3-pass
    gemm_merged<10>(ahA, alA, bhA, blA, lid, wm, wn, acc);
    __syncthreads();   // done reading A/B tiles

    {   // B2 weights via cp.async — overlaps epilogue-1 math below
        const char* s2h = reinterpret_cast<const char*>(g_W2h);
        const char* s2l = reinterpret_cast<const char*>(g_W2l);
#pragma unroll
        for (int i = tid; i < 2688; i += 512) {
            cp16(bhA + i * 16, s2h + i * 16);
            cp16(blA + i * 16, s2l + i * 16);
        }
        CP_COMMIT();
    }

    // epilogue 1: bias+relu, re-split H -> Ah/Al ([m][n] as new [m][k])
#pragma unroll
    for (int mf = 0; mf < 2; mf++) {
#pragma unroll
        for (int nfi = 0; nfi < 4; nfi++) {
            int n = wn * 32 + nfi * 8 + 2 * tg;
            int m = wm * 32 + mf * 16 + g;
            float x0 = fmaxf(acc[mf][nfi][0] + b1s[n],     0.f);
            float x1 = fmaxf(acc[mf][nfi][1] + b1s[n + 1], 0.f);
            uint32_t h, l;
            split2(x0, x1, h, l);
            *reinterpret_cast<uint32_t*>(&Ah[m * K_STR + n]) = h;
            *reinterpret_cast<uint32_t*>(&Al[m * K_STR + n]) = l;
            float x2 = fmaxf(acc[mf][nfi][2] + b1s[n],     0.f);
            float x3 = fmaxf(acc[mf][nfi][3] + b1s[n + 1], 0.f);
            split2(x2, x3, h, l);
            *reinterpret_cast<uint32_t*>(&Ah[(m + 8) * K_STR + n]) = h;
            *reinterpret_cast<uint32_t*>(&Al[(m + 8) * K_STR + n]) = l;
        }
    }
    CP_WAIT0();
    __syncthreads();

#pragma unroll
    for (int a = 0; a < 2; a++)
#pragma unroll
        for (int b = 0; b < 4; b++)
#pragma unroll
            for (int c = 0; c < 4; c++) acc[a][b][c] = 0.f;

    // GEMM2: K=128 (8 k-steps), merged 3-pass
    gemm_merged<8>(ahA, alA, bhA, blA, lid, wm, wn, acc);

    // epilogue 2: bias+relu -> out
#pragma unroll
    for (int mf = 0; mf < 2; mf++) {
#pragma unroll
        for (int nfi = 0; nfi < 4; nfi++) {
            int n = wn * 32 + nfi * 8 + 2 * tg;
            int m = node0 + wm * 32 + mf * 16 + g;
            if (m < N_NODES) {
                float2 v;
                v.x = fmaxf(acc[mf][nfi][0] + b2s[n],     0.f);
                v.y = fmaxf(acc[mf][nfi][1] + b2s[n + 1], 0.f);
                *reinterpret_cast<float2*>(&out[m * 128 + n]) = v;
            }
            if (m + 8 < N_NODES) {
                float2 v;
                v.x = fmaxf(acc[mf][nfi][2] + b2s[n],     0.f);
                v.y = fmaxf(acc[mf][nfi][3] + b2s[n + 1], 0.f);
                *reinterpret_cast<float2*>(&out[(m + 8) * 128 + n]) = v;
            }
        }
    }
}

extern "C" void kernel_launch(void* const* d_in, const int* in_sizes, int n_in,
                              void* d_out, int out_size) {
    const float* edge_logits = (const float*)d_in[0];
    const float* edge_feats  = (const float*)d_in[1];
    const float* node_feats  = (const float*)d_in[2];
    const int*   dst         = (const int*)d_in[3];
    const float* W_et        = (const float*)d_in[4];
    const float* b_et        = (const float*)d_in[5];
    const float* W1          = (const float*)d_in[6];
    const float* b1          = (const float*)d_in[7];
    const float* W2          = (const float*)d_in[8];
    const float* b2          = (const float*)d_in[9];
    float* out = (float*)d_out;

    cudaFuncSetAttribute(mlp_kernel, cudaFuncAttributeMaxDynamicSharedMemorySize,
                         SMEM_BYTES);

    zero_kernel<<<1024, 256>>>();
    wsplit_kernel<<<(128 * K_STR + 255) / 256, 256>>>(W1, W2);
    edge_kernel<<<(N_EDGES * 4) / 256, 256>>>(edge_logits,
                                              (const float4*)edge_feats, dst);
    mlp_kernel<<<(N_NODES + 127) / 128, 512, SMEM_BYTES>>>(
        node_feats, W_et, b_et, b1, b2, out);
    (void)in_sizes; (void)n_in; (void)out_size;
}

// round 13
// speedup vs baseline: 2.2116x; 1.1458x over previous
#include <cuda_runtime.h>
#include <cuda_fp16.h>
#include <cstdint>

#define N_NODES   100000
#define N_EDGES   1600000
#define EDGE_FEAT 16
#define EDGE_HID  32
#define NODE_FEAT 128
#define K_STR     168     // smem K stride (elem): 84 words/row, conflict-free ldmatrix
#define NUM_TILES 782     // ceil(100000/128)

// Scratch (allocation-free rule: __device__ globals)
__device__ float g_wsum[N_NODES * EDGE_FEAT];
__device__ float g_ssum[N_NODES];
__device__ unsigned g_tile;                    // work-stealing counter
// fp16 weights, [n][k] (transposed), zero-padded to K_STR
__device__ __half g_W1f[128 * K_STR];
__device__ __half g_W2f[128 * K_STR];

__device__ __forceinline__ uint32_t sm32(const void* p) {
    return (uint32_t)__cvta_generic_to_shared(p);
}
// fp16 hi/lo split of a float pair (A-side: near-exact 22-bit representation)
__device__ __forceinline__ void split2h(float a, float b, uint32_t& hi, uint32_t& lo) {
    __half2 h = __floats2half2_rn(a, b);
    float2 hf = __half22float2(h);
    __half2 l = __floats2half2_rn(a - hf.x, b - hf.y);
    hi = *reinterpret_cast<uint32_t*>(&h);
    lo = *reinterpret_cast<uint32_t*>(&l);
}
__device__ __forceinline__ void mma16816(float* d, const uint32_t* a,
                                         uint32_t b0, uint32_t b1) {
    asm volatile(
        "mma.sync.aligned.m16n8k16.row.col.f32.f16.f16.f32 "
        "{%0,%1,%2,%3}, {%4,%5,%6,%7}, {%8,%9}, {%0,%1,%2,%3};"
        : "+f"(d[0]), "+f"(d[1]), "+f"(d[2]), "+f"(d[3])
        : "r"(a[0]), "r"(a[1]), "r"(a[2]), "r"(a[3]), "r"(b0), "r"(b1));
}
__device__ __forceinline__ void ldm4(uint32_t* r, uint32_t addr) {
    asm volatile("ldmatrix.sync.aligned.m8n8.x4.shared.b16 {%0,%1,%2,%3}, [%4];"
                 : "=r"(r[0]), "=r"(r[1]), "=r"(r[2]), "=r"(r[3]) : "r"(addr));
}
__device__ __forceinline__ void cp16(uint32_t dst, const void* src) {
    asm volatile("cp.async.cg.shared.global [%0], [%1], 16;"
                 :: "r"(dst), "l"(src));
}
#define CP_COMMIT() asm volatile("cp.async.commit_group;" ::: "memory")
#define CP_WAIT0()  asm volatile("cp.async.wait_group 0;" ::: "memory")

// ---------------------------------------------------------------- zero scratch
__global__ void zero_kernel() {
    int i = blockIdx.x * blockDim.x + threadIdx.x;
    if (i == 0) g_tile = 0;                    // reset work counter each launch
    int stride = gridDim.x * blockDim.x;
    float4 z = make_float4(0.f, 0.f, 0.f, 0.f);
    float4* a = reinterpret_cast<float4*>(g_wsum);
    for (int idx = i; idx < N_NODES * EDGE_FEAT / 4; idx += stride) a[idx] = z;
    float4* b = reinterpret_cast<float4*>(g_ssum);
    for (int idx = i; idx < N_NODES / 4; idx += stride) b[idx] = z;
}

// ------------------------------------------------- weights -> fp16 transposed
__global__ void wsplit_kernel(const float* __restrict__ W1,
                              const float* __restrict__ W2) {
    int i = blockIdx.x * blockDim.x + threadIdx.x;
    if (i >= 128 * K_STR) return;
    int n = i / K_STR, k = i % K_STR;
    g_W1f[i] = __float2half_rn((k < 160) ? W1[k * 128 + n] : 0.f);
    g_W2f[i] = __float2half_rn((k < 128) ? W2[k * 128 + n] : 0.f);
}

// ------------------------------------------------- edge pass: scatter ex, ex*f
__global__ void edge_kernel(const float* __restrict__ logits,
                            const float4* __restrict__ feats4,
                            const int* __restrict__ dst) {
    int t = blockIdx.x * blockDim.x + threadIdx.x;
    int e = t >> 2;
    int q = t & 3;
    if (e >= N_EDGES) return;
    int d = dst[e];
    float ex = __expf(logits[e]);
    float4 f = feats4[e * 4 + q];
    f.x *= ex; f.y *= ex; f.z *= ex; f.w *= ex;
    float* p = g_wsum + d * EDGE_FEAT + q * 4;
    asm volatile("red.global.add.v4.f32 [%0], {%1,%2,%3,%4};"
                 :: "l"(p), "f"(f.x), "f"(f.y), "f"(f.z), "f"(f.w) : "memory");
    if (q == 0)
        asm volatile("red.global.add.f32 [%0], %1;"
                     :: "l"(g_ssum + d), "f"(ex) : "memory");
}

// ---------------------------------------------------------------- fused MLP
// Persistent work-stealing blocks. fp16 2-pass split GEMMs:
//   C = (Ah + Al) @ Bf16   (A hi/lo split exact; only B carries fp16 rounding)
// W1 and W2 both resident in smem for the whole kernel (loaded once).
// 512 threads, 4x4 warp grid, 32x32 warp tiles per 128x128 node tile.
template<int KSTEPS>
__device__ __forceinline__ void gemm2pass(uint32_t ahA, uint32_t alA, uint32_t bA,
                                          int lid, int wm, int wn,
                                          float acc[2][4][4]) {
    const uint32_t aOff = ((wm * 32 + (lid & 15)) * K_STR + 8 * (lid >> 4)) * 2;
    const uint32_t bOff = ((wn * 32 + ((lid >> 4) << 3) + (lid & 7)) * K_STR
                           + 8 * ((lid >> 3) & 1)) * 2;
#pragma unroll 2
    for (int ks = 0; ks < KSTEPS; ks++) {
        uint32_t ah[2][4], al[2][4], b[2][4];
#pragma unroll
        for (int mf = 0; mf < 2; mf++) {
            ldm4(ah[mf], ahA + aOff + mf * 16 * K_STR * 2 + ks * 32);
            ldm4(al[mf], alA + aOff + mf * 16 * K_STR * 2 + ks * 32);
        }
#pragma unroll
        for (int pb = 0; pb < 2; pb++)
            ldm4(b[pb], bA + bOff + pb * 16 * K_STR * 2 + ks * 32);
#pragma unroll
        for (int pb = 0; pb < 2; pb++)
#pragma unroll
            for (int h = 0; h < 2; h++)
#pragma unroll
                for (int mf = 0; mf < 2; mf++) {
                    mma16816(acc[mf][pb * 2 + h], ah[mf], b[pb][2 * h], b[pb][2 * h + 1]);
                    mma16816(acc[mf][pb * 2 + h], al[mf], b[pb][2 * h], b[pb][2 * h + 1]);
                }
    }
}

#define SMEM_BYTES (4 * 128 * K_STR * 2 + 3200)   // 175232

__global__ __launch_bounds__(512, 1)
void mlp_kernel(const float* __restrict__ nf,
                const float* __restrict__ W_et, const float* __restrict__ b_et,
                const float* __restrict__ b1, const float* __restrict__ b2,
                float* __restrict__ out) {
    extern __shared__ char smem[];
    __half* B1f = reinterpret_cast<__half*>(smem);
    __half* B2f = B1f + 128 * K_STR;
    __half* Ah  = B2f + 128 * K_STR;
    __half* Al  = Ah  + 128 * K_STR;
    float* b1s  = reinterpret_cast<float*>(Al + 128 * K_STR);
    float* b2s  = b1s + 128;
    float* Wets = b2s + 128;          // [16][32]
    float* bets = Wets + 512;         // [32]
    __shared__ int s_tile;

    const int tid = threadIdx.x;
    const int wid = tid >> 5, lid = tid & 31;
    const int wm = wid >> 2, wn = wid & 3;   // 4x4 warp grid, 32x32 tiles
    const int g = lid >> 2, tg = lid & 3;
    const uint32_t ahA = sm32(Ah), alA = sm32(Al);
    const uint32_t b1A = sm32(B1f), b2A = sm32(B2f);

    {   // both weight matrices via cp.async, ONCE for the whole kernel
        const char* s1 = reinterpret_cast<const char*>(g_W1f);
        const char* s2 = reinterpret_cast<const char*>(g_W2f);
#pragma unroll
        for (int i = tid; i < 2688; i += 512) {
            cp16(b1A + i * 16, s1 + i * 16);
            cp16(b2A + i * 16, s2 + i * 16);
        }
        CP_COMMIT();
    }
    if (tid < 128) { b1s[tid] = b1[tid]; b2s[tid] = b2[tid]; }
    if (tid < 512) Wets[tid] = W_et[tid];
    if (tid < 32) bets[tid] = b_et[tid];

    const float4* nf4 = reinterpret_cast<const float4*>(nf);

    for (;;) {
        if (tid == 0) s_tile = atomicAdd(&g_tile, 1u);
        __syncthreads();                      // counter visible; prev GEMM2 reads done
        const int tile = s_tile;
        if (tile >= NUM_TILES) break;
        const int node0 = tile * 128;

        {   // A staging: 4 threads/row; ctx inline (8 cols) + nf (32 cols), fp16 split
            int row = tid >> 2, q = tid & 3;
            int node = node0 + row;
            if (node >= N_NODES) node = N_NODES - 1;   // clamp; out stores guarded
            float s = g_ssum[node];
            float inv = (s > 0.f) ? (1.f / s) : 0.f;
            float ind = (s > 0.f) ? 1.f : 0.f;
            float gv[16];
            const float4* gp = reinterpret_cast<const float4*>(g_wsum + node * 16);
#pragma unroll
            for (int k4 = 0; k4 < 4; k4++) {
                float4 v = gp[k4];
                gv[k4 * 4 + 0] = v.x * inv; gv[k4 * 4 + 1] = v.y * inv;
                gv[k4 * 4 + 2] = v.z * inv; gv[k4 * 4 + 3] = v.w * inv;
            }
            float c[8];
            const int j0 = 8 * q;
#pragma unroll
            for (int j = 0; j < 8; j++) c[j] = ind * bets[j0 + j];
#pragma unroll
            for (int k = 0; k < 16; k++) {
                float a = gv[k];
#pragma unroll
                for (int j = 0; j < 8; j++) c[j] = fmaf(a, Wets[k * 32 + j0 + j], c[j]);
            }
#pragma unroll
            for (int j = 0; j < 8; j++) c[j] = (c[j] > 0.f) ? c[j] : (__expf(c[j]) - 1.0f);
#pragma unroll
            for (int t = 0; t < 2; t++) {
                uint32_t h0, l0, h1, l1;
                split2h(c[4 * t], c[4 * t + 1], h0, l0);
                split2h(c[4 * t + 2], c[4 * t + 3], h1, l1);
                *reinterpret_cast<uint2*>(&Ah[row * K_STR + j0 + 4 * t]) = make_uint2(h0, h1);
                *reinterpret_cast<uint2*>(&Al[row * K_STR + j0 + 4 * t]) = make_uint2(l0, l1);
            }
            int kb = 32 + 32 * q;
#pragma unroll
            for (int j = 0; j < 8; j++) {
                int k = kb + 4 * j;
                float4 v = nf4[node * 32 + ((k - 32) >> 2)];
                uint32_t h0, l0, h1, l1;
                split2h(v.x, v.y, h0, l0);
                split2h(v.z, v.w, h1, l1);
                *reinterpret_cast<uint2*>(&Ah[row * K_STR + k]) = make_uint2(h0, h1);
                *reinterpret_cast<uint2*>(&Al[row * K_STR + k]) = make_uint2(l0, l1);
            }
        }
        CP_WAIT0();                           // no-op after first tile
        __syncthreads();

        float acc[2][4][4];
#pragma unroll
        for (int a = 0; a < 2; a++)
#pragma unroll
            for (int b = 0; b < 4; b++)
#pragma unroll
                for (int c = 0; c < 4; c++) acc[a][b][c] = 0.f;

        // GEMM1: K=160 (10 k-steps), 2-pass fp16
        gemm2pass<10>(ahA, alA, b1A, lid, wm, wn, acc);
        __syncthreads();                      // done reading Ah/Al

        // epilogue 1: bias+relu, re-split H -> Ah/Al ([m][n] as new [m][k])
#pragma unroll
        for (int mf = 0; mf < 2; mf++) {
#pragma unroll
            for (int nfi = 0; nfi < 4; nfi++) {
                int n = wn * 32 + nfi * 8 + 2 * tg;
                int m = wm * 32 + mf * 16 + g;
                float x0 = fmaxf(acc[mf][nfi][0] + b1s[n],     0.f);
                float x1 = fmaxf(acc[mf][nfi][1] + b1s[n + 1], 0.f);
                uint32_t h, l;
                split2h(x0, x1, h, l);
                *reinterpret_cast<uint32_t*>(&Ah[m * K_STR + n]) = h;
                *reinterpret_cast<uint32_t*>(&Al[m * K_STR + n]) = l;
                float x2 = fmaxf(acc[mf][nfi][2] + b1s[n],     0.f);
                float x3 = fmaxf(acc[mf][nfi][3] + b1s[n + 1], 0.f);
                split2h(x2, x3, h, l);
                *reinterpret_cast<uint32_t*>(&Ah[(m + 8) * K_STR + n]) = h;
                *reinterpret_cast<uint32_t*>(&Al[(m + 8) * K_STR + n]) = l;
            }
        }
        __syncthreads();

#pragma unroll
        for (int a = 0; a < 2; a++)
#pragma unroll
            for (int b = 0; b < 4; b++)
#pragma unroll
                for (int c = 0; c < 4; c++) acc[a][b][c] = 0.f;

        // GEMM2: K=128 (8 k-steps), 2-pass fp16
        gemm2pass<8>(ahA, alA, b2A, lid, wm, wn, acc);

        // epilogue 2: bias+relu -> out
#pragma unroll
        for (int mf = 0; mf < 2; mf++) {
#pragma unroll
            for (int nfi = 0; nfi < 4; nfi++) {
                int n = wn * 32 + nfi * 8 + 2 * tg;
                int m = node0 + wm * 32 + mf * 16 + g;
                if (m < N_NODES) {
                    float2 v;
                    v.x = fmaxf(acc[mf][nfi][0] + b2s[n],     0.f);
                    v.y = fmaxf(acc[mf][nfi][1] + b2s[n + 1], 0.f);
                    *reinterpret_cast<float2*>(&out[m * 128 + n]) = v;
                }
                if (m + 8 < N_NODES) {
                    float2 v;
                    v.x = fmaxf(acc[mf][nfi][2] + b2s[n],     0.f);
                    v.y = fmaxf(acc[mf][nfi][3] + b2s[n + 1], 0.f);
                    *reinterpret_cast<float2*>(&out[(m + 8) * 128 + n]) = v;
                }
            }
        }
    }
}

extern "C" void kernel_launch(void* const* d_in, const int* in_sizes, int n_in,
                              void* d_out, int out_size) {
    const float* edge_logits = (const float*)d_in[0];
    const float* edge_feats  = (const float*)d_in[1];
    const float* node_feats  = (const float*)d_in[2];
    const int*   dst         = (const int*)d_in[3];
    const float* W_et        = (const float*)d_in[4];
    const float* b_et        = (const float*)d_in[5];
    const float* W1          = (const float*)d_in[6];
    const float* b1          = (const float*)d_in[7];
    const float* W2          = (const float*)d_in[8];
    const float* b2          = (const float*)d_in[9];
    float* out = (float*)d_out;

    cudaFuncSetAttribute(mlp_kernel, cudaFuncAttributeMaxDynamicSharedMemorySize,
                         SMEM_BYTES);

    zero_kernel<<<1024, 256>>>();
    wsplit_kernel<<<(128 * K_STR + 255) / 256, 256>>>(W1, W2);
    edge_kernel<<<(N_EDGES * 4) / 256, 256>>>(edge_logits,
                                              (const float4*)edge_feats, dst);
    mlp_kernel<<<160, 512, SMEM_BYTES>>>(node_feats, W_et, b_et, b1, b2, out);
    (void)in_sizes; (void)n_in; (void)out_size;
}